// round 12
// baseline (speedup 1.0000x reference)
#include <cuda_runtime.h>
#include <cstdint>

// Problem constants (fixed by reference)
#define NN    16384   // n_nodes
#define D_IN  128
#define D_H   64
#define BB    4096    // minibatch

// ---------------------------------------------------------------------------
// Single fused kernel: one block (4 warps) per output row.
//   out[i,:] = ppr[idx[i],:] @ (X @ W + b)
// rewritten via associativity as
//   t = ppr_row_sparse @ X  (TOPK<=128 nonzeros);  out = t @ W + rowsum * b
//
// Stages (all intra-block):
//  0. idx dtype detect: odd int32 words of entries 0..255 (word idx 1..511,
//     in-bounds whether idx is int32 [4096 words] or int64 [8192 words]).
//     int64 values <16384 => all zero; P(false|int32) = (1/16384)^256 ~ 0.
//     L2-hot broadcast after the first block. Then row = idx[blockIdx.x].
//  1. Scan: each warp streams its 16KB quarter-row as 8 uint4 in flight
//     (__ldcs), integer-OR zero test (values nonneg, zeros exact +0.0f),
//     nonzeros appended to a per-warp smem list. (Measured-best loop.)
//  2. Replay: per nonzero one LDG.128 of the X row (L2-hot); lane owns 4 of
//     128 t-columns. Block-reduce across warps -> sT[128], rowsum.
//  3. Epilogue: out[i,c] = sum_k sT[k]*W[k,c] + rowsum*b[c].
//
// __launch_bounds__(128,12): cap regs ~42 so 12 blocks (48 warps) are
// resident per SM — +20% concurrent scanners to cover the replay/epilogue
// phases of other blocks, with the MLP=8 scan batch UNCHANGED (unlike the
// failed R8 experiment which shrank the batch to buy occupancy).
// ---------------------------------------------------------------------------
__global__ void __launch_bounds__(128, 12) fused_kernel(const float* __restrict__ ppr,
                                                        const float* __restrict__ X,
                                                        const float* __restrict__ W,
                                                        const float* __restrict__ b,
                                                        const int* __restrict__ idx32,
                                                        float* __restrict__ out) {
    __shared__ float vbuf[4][160];
    __shared__ int   jbuf[4][160];
    __shared__ int   cnt[4];
    __shared__ float red[4][D_IN];
    __shared__ float rsum[4];
    __shared__ float sT[D_IN];
    __shared__ float part[2][D_H];
    __shared__ int   s_is64;

    const int i    = blockIdx.x;
    const int tid  = threadIdx.x;
    const int lane = tid & 31;
    const int warp = tid >> 5;

    // ---- Stage 0: dtype detect + row fetch ----
    if (tid == 0) s_is64 = 1;
    if (lane == 0) cnt[warp] = 0;
    __syncthreads();
    if ((idx32[2 * tid + 1] | idx32[2 * (tid + 128) + 1]) != 0) s_is64 = 0;
    __syncthreads();
    const int row = s_is64 ? idx32[2 * i] : idx32[i];

    const uint4* rowp = reinterpret_cast<const uint4*>(ppr) + (size_t)row * (NN / 4);
    const int base = warp * 1024;   // this warp's quarter: 1024 uint4 = 16KB

    // ---- Stage 1: scan (measured-best structure, MLP=8) ----
    for (int it = 0; it < 32; it += 8) {
        uint4 buf[8];
#pragma unroll
        for (int u = 0; u < 8; u++)
            buf[u] = __ldcs(rowp + base + (it + u) * 32 + lane);

#pragma unroll
        for (int u = 0; u < 8; u++) {
            const uint4 q = buf[u];
            if (q.x | q.y | q.z | q.w) {
                const int j0 = (base + (it + u) * 32 + lane) * 4;
                if (q.x) { int t = atomicAdd(&cnt[warp], 1); if (t < 160) { jbuf[warp][t] = j0;     vbuf[warp][t] = __uint_as_float(q.x); } }
                if (q.y) { int t = atomicAdd(&cnt[warp], 1); if (t < 160) { jbuf[warp][t] = j0 + 1; vbuf[warp][t] = __uint_as_float(q.y); } }
                if (q.z) { int t = atomicAdd(&cnt[warp], 1); if (t < 160) { jbuf[warp][t] = j0 + 2; vbuf[warp][t] = __uint_as_float(q.z); } }
                if (q.w) { int t = atomicAdd(&cnt[warp], 1); if (t < 160) { jbuf[warp][t] = j0 + 3; vbuf[warp][t] = __uint_as_float(q.w); } }
            }
        }
    }
    __syncwarp();

    // ---- Stage 2: replay vs X (L2-hot); lane owns 4 t-columns ----
    float4 acc = make_float4(0.f, 0.f, 0.f, 0.f);
    float  srow = 0.0f;
    const float4* X4 = reinterpret_cast<const float4*>(X);
    const int n = min(cnt[warp], 160);
#pragma unroll 2
    for (int k = 0; k < n; k++) {
        const float v = vbuf[warp][k];
        const float4 xr = __ldg(X4 + (size_t)jbuf[warp][k] * (D_IN / 4) + lane);
        acc.x += v * xr.x; acc.y += v * xr.y;
        acc.z += v * xr.z; acc.w += v * xr.w;
        srow += v;
    }
    reinterpret_cast<float4*>(red[warp])[lane] = acc;
    if (lane == 0) rsum[warp] = srow;
    __syncthreads();

    // combine warps: thread c owns t-column c
    sT[tid] = red[0][tid] + red[1][tid] + red[2][tid] + red[3][tid];
    __syncthreads();

    // ---- Stage 3: epilogue out = sT @ W + rowsum*b ----
    {
        const int c = tid & 63;
        const int h = tid >> 6;            // k-half 0 or 1
        float p = 0.0f;
        const float* Wh = W + (h * 64) * D_H + c;
#pragma unroll 16
        for (int k = 0; k < 64; k++)
            p += sT[h * 64 + k] * __ldg(Wh + k * D_H);
        part[h][c] = p;
        __syncthreads();
        if (tid < D_H) {
            const float rs = rsum[0] + rsum[1] + rsum[2] + rsum[3];
            out[(size_t)i * D_H + tid] =
                part[0][tid] + part[1][tid] + rs * __ldg(b + tid);
        }
    }
}

// ---------------------------------------------------------------------------
extern "C" void kernel_launch(void* const* d_in, const int* in_sizes, int n_in,
                              void* d_out, int out_size) {
    const float* X   = (const float*)d_in[0];
    const float* ppr = (const float*)d_in[1];
    const float* W   = (const float*)d_in[2];
    const float* b   = (const float*)d_in[3];
    const int*   idx = (const int*)d_in[4];
    float* out = (float*)d_out;

    fused_kernel<<<BB, 128>>>(ppr, X, W, b, idx, out);
}

// round 13
// speedup vs baseline: 1.1416x; 1.1416x over previous
#include <cuda_runtime.h>
#include <cstdint>

// Problem constants (fixed by reference)
#define NN    16384   // n_nodes
#define D_IN  128
#define D_H   64
#define BB    4096    // minibatch

// ---------------------------------------------------------------------------
// Single fused kernel: one block (4 warps) per output row.
//   out[i,:] = ppr[idx[i],:] @ (X @ W + b)
//            = (ppr_row_sparse @ X) @ W + rowsum * b     (TOPK<=128 nonzeros)
//
//  0. idx dtype detect (odd words of entries 0..255 — in-bounds for both
//     int32 [4096 words] and int64 [8192 words]; P(false|int32)~0).
//  1. Scan (FROZEN, measured-best): per warp 8 uint4 in flight (__ldcs),
//     integer-OR zero test (values nonneg, zeros exact +0.0f), nonzeros to
//     per-warp smem lists. Plain launch_bounds(128) — regs=48 config; the
//     occupancy-cap variants (R8, R12) both regressed.
//  2. Replay v2: lists zero-padded by 8; batches of 8 independent LDG.128 of
//     X rows (L2-hot) -> latency-hidden, phase ~4x shorter than the serial
//     unroll-2 version.
//  3. Epilogue v2: thread = (column-quad, k-group): 16 LDG.128 of W + 16 LDS
//     + 64 FMA, then 2KB smem k-group reduction. 4x fewer load instructions
//     than the scalar version.
// ---------------------------------------------------------------------------
__global__ void __launch_bounds__(128) fused_kernel(const float* __restrict__ ppr,
                                                    const float* __restrict__ X,
                                                    const float* __restrict__ W,
                                                    const float* __restrict__ b,
                                                    const int* __restrict__ idx32,
                                                    float* __restrict__ out) {
    __shared__ float vbuf[4][168];     // 160 cap + 8 zero-pad
    __shared__ int   jbuf[4][168];
    __shared__ int   cnt[4];
    __shared__ float red[4][D_IN];
    __shared__ float rsum[4];
    __shared__ float sT[D_IN];
    __shared__ float part[8][D_H];     // k-group partials
    __shared__ int   s_is64;

    const int i    = blockIdx.x;
    const int tid  = threadIdx.x;
    const int lane = tid & 31;
    const int warp = tid >> 5;

    // ---- Stage 0: dtype detect + row fetch ----
    if (tid == 0) s_is64 = 1;
    if (lane == 0) cnt[warp] = 0;
    __syncthreads();
    if ((idx32[2 * tid + 1] | idx32[2 * (tid + 128) + 1]) != 0) s_is64 = 0;
    __syncthreads();
    const int row = s_is64 ? idx32[2 * i] : idx32[i];

    const uint4* rowp = reinterpret_cast<const uint4*>(ppr) + (size_t)row * (NN / 4);
    const int base = warp * 1024;   // this warp's quarter: 1024 uint4 = 16KB

    // ---- Stage 1: scan (frozen structure, MLP=8) ----
    for (int it = 0; it < 32; it += 8) {
        uint4 buf[8];
#pragma unroll
        for (int u = 0; u < 8; u++)
            buf[u] = __ldcs(rowp + base + (it + u) * 32 + lane);

#pragma unroll
        for (int u = 0; u < 8; u++) {
            const uint4 q = buf[u];
            if (q.x | q.y | q.z | q.w) {
                const int j0 = (base + (it + u) * 32 + lane) * 4;
                if (q.x) { int t = atomicAdd(&cnt[warp], 1); if (t < 160) { jbuf[warp][t] = j0;     vbuf[warp][t] = __uint_as_float(q.x); } }
                if (q.y) { int t = atomicAdd(&cnt[warp], 1); if (t < 160) { jbuf[warp][t] = j0 + 1; vbuf[warp][t] = __uint_as_float(q.y); } }
                if (q.z) { int t = atomicAdd(&cnt[warp], 1); if (t < 160) { jbuf[warp][t] = j0 + 2; vbuf[warp][t] = __uint_as_float(q.z); } }
                if (q.w) { int t = atomicAdd(&cnt[warp], 1); if (t < 160) { jbuf[warp][t] = j0 + 3; vbuf[warp][t] = __uint_as_float(q.w); } }
            }
        }
    }
    __syncwarp();

    // zero-pad 8 entries past the end so replay batches need no tail handling
    const int n = min(cnt[warp], 160);
    if (lane < 8) { vbuf[warp][n + lane] = 0.0f; jbuf[warp][n + lane] = 0; }
    __syncwarp();

    // ---- Stage 2: replay v2 — batches of 8 independent LDG.128 ----
    float4 acc = make_float4(0.f, 0.f, 0.f, 0.f);
    float  srow = 0.0f;
    const float4* X4 = reinterpret_cast<const float4*>(X);
    for (int k0 = 0; k0 < n; k0 += 8) {
        float  vv[8];
        float4 xr[8];
#pragma unroll
        for (int u = 0; u < 8; u++) {
            vv[u] = vbuf[warp][k0 + u];
            xr[u] = __ldg(X4 + (size_t)jbuf[warp][k0 + u] * (D_IN / 4) + lane);
        }
#pragma unroll
        for (int u = 0; u < 8; u++) {
            acc.x += vv[u] * xr[u].x; acc.y += vv[u] * xr[u].y;
            acc.z += vv[u] * xr[u].z; acc.w += vv[u] * xr[u].w;
            srow += vv[u];
        }
    }
    reinterpret_cast<float4*>(red[warp])[lane] = acc;
    if (lane == 0) rsum[warp] = srow;
    __syncthreads();

    // combine warps: thread c owns t-column c
    sT[tid] = red[0][tid] + red[1][tid] + red[2][tid] + red[3][tid];
    __syncthreads();

    // ---- Stage 3: epilogue v2 — out = sT @ W + rowsum*b ----
    {
        const int cq = tid & 15;          // column quad (4 cols each)
        const int kg = tid >> 4;          // k-group of 16
        const float4* W4 = reinterpret_cast<const float4*>(W);  // W4[k*16 + cq]
        float4 a4 = make_float4(0.f, 0.f, 0.f, 0.f);
#pragma unroll
        for (int kk = 0; kk < 16; kk++) {
            const int k = kg * 16 + kk;
            const float tv = sT[k];
            const float4 w4 = __ldg(W4 + k * 16 + cq);
            a4.x += tv * w4.x; a4.y += tv * w4.y;
            a4.z += tv * w4.z; a4.w += tv * w4.w;
        }
        reinterpret_cast<float4*>(part[kg])[cq] = a4;
        __syncthreads();
        if (tid < D_H) {
            const float rs = rsum[0] + rsum[1] + rsum[2] + rsum[3];
            float s = rs * __ldg(b + tid);
#pragma unroll
            for (int g = 0; g < 8; g++) s += part[g][tid];
            out[(size_t)i * D_H + tid] = s;
        }
    }
}

// ---------------------------------------------------------------------------
extern "C" void kernel_launch(void* const* d_in, const int* in_sizes, int n_in,
                              void* d_out, int out_size) {
    const float* X   = (const float*)d_in[0];
    const float* ppr = (const float*)d_in[1];
    const float* W   = (const float*)d_in[2];
    const float* b   = (const float*)d_in[3];
    const int*   idx = (const int*)d_in[4];
    float* out = (float*)d_out;

    fused_kernel<<<BB, 128>>>(ppr, X, W, b, idx, out);
}

// round 14
// speedup vs baseline: 1.1582x; 1.0146x over previous
#include <cuda_runtime.h>
#include <cstdint>

// Problem constants (fixed by reference)
#define NN    16384   // n_nodes
#define D_IN  128
#define D_H   64
#define BB    4096    // minibatch

// ---------------------------------------------------------------------------
// Single fused kernel: one block (4 warps) per output row.
//   out[i,:] = ppr[idx[i],:] @ (X @ W + b)
//            = (ppr_row_sparse @ X) @ W + rowsum * b     (TOPK<=128 nonzeros)
//
//  0. idx dtype detect (odd words of entries 0..255 — in-bounds for both
//     int32 [4096 words] and int64 [8192 words]; P(false|int32)~0).
//  1. Scan + INLINE process: per warp 8 uint4 in flight (__ldcs); per
//     element, ballot finds the (rare, ~1/warp-step) nonzeros; (v, j)
//     broadcast by shfl; every lane does acc4 += v * X4[j*32+lane]
//     (coalesced 512B L2-hot read of X row j). No separate replay phase —
//     processing interleaves between DRAM load batches, so DRAM duty stays
//     at the scan plateau (the list-replay variant diluted it to 55%).
//  2. Combine warps -> sT[128], rowsum.
//  3. Epilogue (validated in R13): thread = (column-quad, k-group):
//     16 LDG.128 of W + 64 FMA, smem k-group reduction, + rowsum*b.
// ---------------------------------------------------------------------------
__global__ void __launch_bounds__(128) fused_kernel(const float* __restrict__ ppr,
                                                    const float* __restrict__ X,
                                                    const float* __restrict__ W,
                                                    const float* __restrict__ b,
                                                    const int* __restrict__ idx32,
                                                    float* __restrict__ out) {
    __shared__ float red[4][D_IN];
    __shared__ float rsum[4];
    __shared__ float sT[D_IN];
    __shared__ float part[8][D_H];     // k-group partials
    __shared__ int   s_is64;

    const int i    = blockIdx.x;
    const int tid  = threadIdx.x;
    const int lane = tid & 31;
    const int warp = tid >> 5;

    // ---- Stage 0: dtype detect + row fetch ----
    if (tid == 0) s_is64 = 1;
    __syncthreads();
    if ((idx32[2 * tid + 1] | idx32[2 * (tid + 128) + 1]) != 0) s_is64 = 0;
    __syncthreads();
    const int row = s_is64 ? idx32[2 * i] : idx32[i];

    const uint4*  rowp = reinterpret_cast<const uint4*>(ppr) + (size_t)row * (NN / 4);
    const float4* X4   = reinterpret_cast<const float4*>(X);
    const int base = warp * 1024;   // this warp's quarter: 1024 uint4 = 16KB

    // ---- Stage 1: scan with inline processing ----
    float4 acc = make_float4(0.f, 0.f, 0.f, 0.f);
    float  srow = 0.0f;

    for (int it = 0; it < 32; it += 8) {
        uint4 buf[8];
#pragma unroll
        for (int u = 0; u < 8; u++)
            buf[u] = __ldcs(rowp + base + (it + u) * 32 + lane);

#pragma unroll
        for (int u = 0; u < 8; u++) {
            const uint4 q = buf[u];
            const int j0 = (base + (it + u) * 32 + lane) * 4;
            float vs[4] = {__uint_as_float(q.x), __uint_as_float(q.y),
                           __uint_as_float(q.z), __uint_as_float(q.w)};
#pragma unroll
            for (int e = 0; e < 4; e++) {
                unsigned m = __ballot_sync(0xffffffffu, vs[e] != 0.0f);
                while (m) {
                    const int src = __ffs(m) - 1;
                    m &= m - 1;
                    const float v = __shfl_sync(0xffffffffu, vs[e], src);
                    const int   j = __shfl_sync(0xffffffffu, j0 + e, src);
                    const float4 xr = __ldg(X4 + (size_t)j * 32 + lane);
                    acc.x += v * xr.x; acc.y += v * xr.y;
                    acc.z += v * xr.z; acc.w += v * xr.w;
                    srow += v;
                }
            }
        }
    }

    reinterpret_cast<float4*>(red[warp])[lane] = acc;
    if (lane == 0) rsum[warp] = srow;
    __syncthreads();

    // ---- Stage 2: combine warps; thread c owns t-column c ----
    sT[tid] = red[0][tid] + red[1][tid] + red[2][tid] + red[3][tid];
    __syncthreads();

    // ---- Stage 3: epilogue — out = sT @ W + rowsum*b ----
    {
        const int cq = tid & 15;          // column quad (4 cols each)
        const int kg = tid >> 4;          // k-group of 16
        const float4* W4 = reinterpret_cast<const float4*>(W);  // W4[k*16 + cq]
        float4 a4 = make_float4(0.f, 0.f, 0.f, 0.f);
#pragma unroll
        for (int kk = 0; kk < 16; kk++) {
            const int k = kg * 16 + kk;
            const float tv = sT[k];
            const float4 w4 = __ldg(W4 + k * 16 + cq);
            a4.x += tv * w4.x; a4.y += tv * w4.y;
            a4.z += tv * w4.z; a4.w += tv * w4.w;
        }
        reinterpret_cast<float4*>(part[kg])[cq] = a4;
        __syncthreads();
        if (tid < D_H) {
            const float rs = rsum[0] + rsum[1] + rsum[2] + rsum[3];
            float s = rs * __ldg(b + tid);
#pragma unroll
            for (int g = 0; g < 8; g++) s += part[g][tid];
            out[(size_t)i * D_H + tid] = s;
        }
    }
}

// ---------------------------------------------------------------------------
extern "C" void kernel_launch(void* const* d_in, const int* in_sizes, int n_in,
                              void* d_out, int out_size) {
    const float* X   = (const float*)d_in[0];
    const float* ppr = (const float*)d_in[1];
    const float* W   = (const float*)d_in[2];
    const float* b   = (const float*)d_in[3];
    const int*   idx = (const int*)d_in[4];
    float* out = (float*)d_out;

    fused_kernel<<<BB, 128>>>(ppr, X, W, b, idx, out);
}